// round 14
// baseline (speedup 1.0000x reference)
#include <cuda_runtime.h>
#include <cuda_fp16.h>
#include <cfloat>
#include <cstdint>
#include <math.h>

#define BB 4
#define TT 2048
#define EE 1024
#define HH 16
#define DH 64
#define MROWS (BB*TT)        // 8192

typedef __half  f16;
typedef __half2 f162;

// ============================ scratch =====================================
__device__ float g_x1 [(size_t)MROWS*EE];
__device__ f16  g_qh  [(size_t)BB*HH*TT*DH];
__device__ f16  g_kh  [(size_t)BB*HH*TT*DH];
__device__ f16  g_vh  [(size_t)BB*HH*TT*DH];
__device__ f16  g_h   [(size_t)MROWS*EE];
__device__ f16  g_att [(size_t)MROWS*EE];
__device__ f16  g_ff  [(size_t)MROWS*4096];
__device__ f16  g_wqkvT[(size_t)3072*EE];
__device__ f16  g_WpT[(size_t)EE*EE];
__device__ f16  g_W1T[(size_t)4096*EE];
__device__ f16  g_W2T[(size_t)EE*4096];

// ============================ helpers =====================================
__device__ __forceinline__ uint32_t smem_to_u32(const void* p) {
    uint32_t a;
    asm("{ .reg .u64 t; cvta.to.shared.u64 t, %1; cvt.u32.u64 %0, t; }"
        : "=r"(a) : "l"(p));
    return a;
}

#define SWZ128(o) ((o) ^ (((o) >> 3) & 0x70))

#define CP16(dst, src) \
    asm volatile("cp.async.cg.shared.global [%0], [%1], 16;" \
        :: "r"(dst), "l"(src) : "memory")
#define CP_COMMIT() asm volatile("cp.async.commit_group;" ::: "memory")
#define CP_WAIT(N)  asm volatile("cp.async.wait_group %0;" :: "n"(N) : "memory")

__device__ __forceinline__ void ldsm_x4(uint32_t addr,
    uint32_t& r0, uint32_t& r1, uint32_t& r2, uint32_t& r3) {
    asm volatile("ldmatrix.sync.aligned.m8n8.x4.shared.b16 {%0,%1,%2,%3}, [%4];"
        : "=r"(r0), "=r"(r1), "=r"(r2), "=r"(r3) : "r"(addr));
}
__device__ __forceinline__ void ldsm_x4_trans(uint32_t addr,
    uint32_t& r0, uint32_t& r1, uint32_t& r2, uint32_t& r3) {
    asm volatile("ldmatrix.sync.aligned.m8n8.x4.trans.shared.b16 {%0,%1,%2,%3}, [%4];"
        : "=r"(r0), "=r"(r1), "=r"(r2), "=r"(r3) : "r"(addr));
}

__device__ __forceinline__ void mma_f16(float* c, const uint32_t* a, const uint32_t* b) {
    asm volatile(
        "mma.sync.aligned.m16n8k16.row.col.f32.f16.f16.f32 "
        "{%0,%1,%2,%3}, {%4,%5,%6,%7}, {%8,%9}, {%0,%1,%2,%3};"
        : "+f"(c[0]), "+f"(c[1]), "+f"(c[2]), "+f"(c[3])
        : "r"(a[0]), "r"(a[1]), "r"(a[2]), "r"(a[3]), "r"(b[0]), "r"(b[1]));
}

// fp16-accumulate MMA (full rate on sm_103a legacy tensor path)
__device__ __forceinline__ void mma_f16h(uint32_t* c, const uint32_t* a, const uint32_t* b) {
    asm volatile(
        "mma.sync.aligned.m16n8k16.row.col.f16.f16.f16.f16 "
        "{%0,%1}, {%2,%3,%4,%5}, {%6,%7}, {%0,%1};"
        : "+r"(c[0]), "+r"(c[1])
        : "r"(a[0]), "r"(a[1]), "r"(a[2]), "r"(a[3]), "r"(b[0]), "r"(b[1]));
}

__device__ __forceinline__ float ex2f(float x) {
    float y;
    asm("ex2.approx.ftz.f32 %0, %1;" : "=f"(y) : "f"(x));
    return y;
}

// ============================ LayerNorm body ================================
__device__ __forceinline__ void ln_body(
    const float* __restrict__ x, const float* __restrict__ g,
    const float* __restrict__ b, f16* __restrict__ oh,
    int row, float* sred)
{
    int tid = threadIdx.x;
    float4 xv = ((const float4*)(x + (size_t)row * EE))[tid];
    float s  = xv.x + xv.y + xv.z + xv.w;
    float s2 = xv.x*xv.x + xv.y*xv.y + xv.z*xv.z + xv.w*xv.w;
    #pragma unroll
    for (int o = 16; o > 0; o >>= 1) {
        s  += __shfl_xor_sync(0xffffffffu, s,  o);
        s2 += __shfl_xor_sync(0xffffffffu, s2, o);
    }
    float* rs = sred;
    float* rs2 = sred + 8;
    int w = tid >> 5;
    if ((tid & 31) == 0) { rs[w] = s; rs2[w] = s2; }
    __syncthreads();
    s = 0.f; s2 = 0.f;
    #pragma unroll
    for (int i = 0; i < 8; i++) { s += rs[i]; s2 += rs2[i]; }
    float mean = s * (1.0f/1024.0f);
    float var  = s2 * (1.0f/1024.0f) - mean*mean;
    float inv  = rsqrtf(var + 1e-5f);
    float4 gv = ((const float4*)g)[tid];
    float4 bv = ((const float4*)b)[tid];
    float o0 = (xv.x - mean)*inv*gv.x + bv.x;
    float o1 = (xv.y - mean)*inv*gv.y + bv.y;
    float o2 = (xv.z - mean)*inv*gv.z + bv.z;
    float o3 = (xv.w - mean)*inv*gv.w + bv.w;
    size_t base = (size_t)row * EE + tid*4;
    *(f162*)(oh+base)   = __float22half2_rn(make_float2(o0,o1));
    *(f162*)(oh+base+2) = __float22half2_rn(make_float2(o2,o3));
}

// ============== transpose+convert body: fp32 [K,N] -> fp16 [N,K] ===========
__device__ __forceinline__ void convt_body(
    const float* __restrict__ src, f16* __restrict__ dh, int K, int N,
    int bx, int by, float* tbuf)
{
    float (*t)[33] = (float (*)[33]) tbuf;
    int x = threadIdx.x & 31, y = threadIdx.x >> 5;
    int n0 = bx * 32, k0 = by * 32;
    #pragma unroll
    for (int i = 0; i < 32; i += 8)
        t[y+i][x] = src[(size_t)(k0 + y + i) * N + n0 + x];
    __syncthreads();
    #pragma unroll
    for (int i = 0; i < 32; i += 8) {
        float vv = t[x][y+i];
        dh[(size_t)(n0 + y + i) * K + k0 + x] = __float2half_rn(vv);
    }
}

// ==== fused prep: LN1 + qkv-weight pack/transpose + 3 weight converts ======
#define PREP_BLOCKS (8192 + 3072 + 1024 + 4096 + 4096)

__global__ void __launch_bounds__(256) prep_kernel(
    const float* __restrict__ x, const float* __restrict__ ln1_g,
    const float* __restrict__ ln1_b, f16* __restrict__ h_,
    const float* __restrict__ Wq, const float* __restrict__ Wk,
    const float* __restrict__ Wv, f16* __restrict__ wqT,
    const float* __restrict__ Wp, f16* __restrict__ WpT,
    const float* __restrict__ W1, f16* __restrict__ W1T,
    const float* __restrict__ W2, f16* __restrict__ W2T)
{
    __shared__ float sbuf[32*33];
    int bid = blockIdx.x;
    if (bid < 8192) {
        ln_body(x, ln1_g, ln1_b, h_, bid, sbuf);
        return;
    }
    bid -= 8192;
    if (bid < 3072) {
        float (*t)[33] = (float (*)[33]) sbuf;
        int xx = threadIdx.x & 31, yy = threadIdx.x >> 5;
        int bx = bid & 31;
        int byz = bid >> 5;
        int by = byz & 1;
        int z  = byz >> 1;
        int tq = z >> 4, hh2 = z & 15;
        const float* W = (tq == 0) ? Wq : (tq == 1) ? Wk : Wv;
        int e0 = bx * 32, d0 = by * 32;
        #pragma unroll
        for (int i = 0; i < 32; i += 8)
            t[yy+i][xx] = W[(size_t)hh2 * EE * DH + (size_t)(e0 + yy + i) * DH + d0 + xx];
        __syncthreads();
        #pragma unroll
        for (int i = 0; i < 32; i += 8) {
            int rown = tq*1024 + hh2*64 + d0 + yy + i;
            wqT[(size_t)rown * EE + e0 + xx] = __float2half_rn(t[xx][yy+i]);
        }
        return;
    }
    bid -= 3072;
    if (bid < 1024) { convt_body(Wp, WpT, 1024, 1024, bid & 31, bid >> 5, sbuf); return; }
    bid -= 1024;
    if (bid < 4096) { convt_body(W1, W1T, 1024, 4096, bid & 127, bid >> 7, sbuf); return; }
    bid -= 4096;
    convt_body(W2, W2T, 4096, 1024, bid & 31, bid >> 5, sbuf);
}

// ==================== standalone LN (for LN2) ==============================
__global__ void __launch_bounds__(256) ln_kernel(
    const float* __restrict__ x, const float* __restrict__ g,
    const float* __restrict__ b, f16* __restrict__ oh)
{
    __shared__ float sred[16];
    ln_body(x, g, b, oh, blockIdx.x, sred);
}

// ===== HMMA GEMM: C[M,N] = A[M,K] * B[N,K]^T, fp16, 128x128 tile, 3-stage ==
// 256 threads / 8 warps, warp tile 32x64; 2 CTAs/SM. fp16 accumulate within
// each K=64 chunk (full-rate HMMA), promoted to fp32 once per chunk.
enum { EPI_QKV = 0, EPI_BIAS_RESID = 1, EPI_RELU = 2 };

#define KCHUNK 64
#define A_TILE_BYTES 16384                // 128 rows x 64 fp16
#define B_TILE_BYTES 16384                // 128 rows x 64 fp16
#define STAGE_BYTES (A_TILE_BYTES + B_TILE_BYTES)   // 32768
#define NSTAGE 3
#define SMEM_GEMM (NSTAGE*STAGE_BYTES + 1024)       // 99328

template<int EPI>
__global__ void __launch_bounds__(256, 2) gemm_tc(
    const f16* __restrict__ A, const f16* __restrict__ B,
    int K, int N,
    const float* __restrict__ bias, const float* __restrict__ resid,
    float* __restrict__ Cf, f16* __restrict__ Of,
    f16* __restrict__ oqh, f16* __restrict__ okh, f16* __restrict__ ovh)
{
    extern __shared__ char smraw[];
    uint32_t raw = smem_to_u32(smraw);
    uint32_t sbase = (raw + 1023u) & ~1023u;

    int tid  = threadIdx.x;
    int wid  = tid >> 5, lane = tid & 31;
    int m0 = blockIdx.y * 128;
    int n0 = blockIdx.x * 128;
    int mw = (wid & 3) * 32;       // warp row offset (4 warps in M)
    int nw = (wid >> 2) * 64;      // warp col offset (2 warps in N)

    const f16* Ap = A + (size_t)m0 * K;
    const f16* Bp = B + (size_t)n0 * K;

    const int nk = K / KCHUNK;

    auto prefetch = [&](int c) {
        uint32_t st = sbase + (uint32_t)(c % NSTAGE) * STAGE_BYTES;
        int kc = c * KCHUNK;
        #pragma unroll
        for (int it = 0; it < 4; it++) {          // A: 1024 16B units
            int u = tid + it * 256;
            int r = u >> 3, cc = u & 7;
            uint32_t so = st + SWZ128((uint32_t)(r * 128 + cc * 16));
            CP16(so, Ap + (size_t)r * K + kc + cc * 8);
        }
        #pragma unroll
        for (int it = 0; it < 4; it++) {          // B: 1024 16B units
            int u = tid + it * 256;
            int r = u >> 3, cc = u & 7;
            uint32_t so = st + A_TILE_BYTES + SWZ128((uint32_t)(r * 128 + cc * 16));
            CP16(so, Bp + (size_t)r * K + kc + cc * 8);
        }
    };

    float acc[2][8][4];
    #pragma unroll
    for (int mt = 0; mt < 2; mt++)
        #pragma unroll
        for (int nt = 0; nt < 8; nt++)
            #pragma unroll
            for (int q = 0; q < 4; q++) acc[mt][nt][q] = 0.f;

    prefetch(0); CP_COMMIT();
    prefetch(1); CP_COMMIT();

    int g  = lane >> 3;   // ldmatrix lane group
    int lr = lane & 7;

    for (int c = 0; c < nk; c++) {
        CP_WAIT(1);                 // chunk c resident (c+1 may fly)
        __syncthreads();            // all warps past chunk c-1 reads + visibility
        if (c + 2 < nk) { prefetch(c + 2); CP_COMMIT(); }   // slot (c-1)%3: safe

        uint32_t st = sbase + (uint32_t)(c % NSTAGE) * STAGE_BYTES;
        uint32_t aB = st, bB = st + A_TILE_BYTES;

        // fp16 chunk accumulators
        uint32_t c16[2][8][2];
        #pragma unroll
        for (int mt = 0; mt < 2; mt++)
            #pragma unroll
            for (int nt = 0; nt < 8; nt++) { c16[mt][nt][0] = 0; c16[mt][nt][1] = 0; }

        #pragma unroll
        for (int ks = 0; ks < 4; ks++) {
            uint32_t ah[2][4];
            #pragma unroll
            for (int mt = 0; mt < 2; mt++) {
                uint32_t off = SWZ128((uint32_t)(
                    (mw + mt*16 + (g & 1)*8 + lr) * 128 + ks*32 + (g >> 1)*16));
                ldsm_x4(aB + off, ah[mt][0], ah[mt][1], ah[mt][2], ah[mt][3]);
            }
            #pragma unroll
            for (int bhf = 0; bhf < 2; bhf++) {     // B in halves (reg pressure)
                uint32_t bh[4][2];
                #pragma unroll
                for (int pp = 0; pp < 2; pp++) {
                    int p = bhf*2 + pp;
                    uint32_t off = SWZ128((uint32_t)(
                        (nw + p*16 + (g >> 1)*8 + lr) * 128 + ks*32 + (g & 1)*16));
                    uint32_t r0, r1, r2, r3;
                    ldsm_x4(bB + off, r0, r1, r2, r3);
                    bh[pp*2][0] = r0; bh[pp*2][1] = r1;
                    bh[pp*2+1][0] = r2; bh[pp*2+1][1] = r3;
                }
                #pragma unroll
                for (int mt = 0; mt < 2; mt++)
                    #pragma unroll
                    for (int nt2 = 0; nt2 < 4; nt2++)
                        mma_f16h(c16[mt][bhf*4 + nt2], ah[mt], bh[nt2]);
            }
        }

        // promote chunk sum into fp32 accumulators
        #pragma unroll
        for (int mt = 0; mt < 2; mt++)
            #pragma unroll
            for (int nt = 0; nt < 8; nt++) {
                f162 p0 = *(f162*)&c16[mt][nt][0];
                f162 p1 = *(f162*)&c16[mt][nt][1];
                float2 f0 = __half22float2(p0);
                float2 f1 = __half22float2(p1);
                acc[mt][nt][0] += f0.x;
                acc[mt][nt][1] += f0.y;
                acc[mt][nt][2] += f1.x;
                acc[mt][nt][3] += f1.y;
            }
    }

    // ------------------------------ epilogue -------------------------------
    int qr = lane >> 2;        // 0..7
    int qc = (lane & 3) * 2;   // 0,2,4,6
    #pragma unroll
    for (int mt = 0; mt < 2; mt++) {
        #pragma unroll
        for (int nt = 0; nt < 8; nt++) {
            int col = n0 + nw + nt*8 + qc;
            #pragma unroll
            for (int half = 0; half < 2; half++) {
                int m = m0 + mw + mt*16 + qr + half*8;
                float v0 = acc[mt][nt][half*2 + 0];
                float v1 = acc[mt][nt][half*2 + 1];
                if (EPI == EPI_QKV) {
                    int bb = m >> 11, tt = m & 2047;
                    int t = col >> 10, nn = col & 1023, h = nn >> 6, d0 = nn & 63;
                    size_t o = (((size_t)(bb*HH + h)) * TT + tt) * DH + d0;
                    // q pre-scaled by E^-0.5 * log2(e) for ex2-softmax
                    float s = (t == 0) ? 0.045084439f : 1.0f;
                    f16* dst = (t == 0) ? oqh : (t == 1) ? okh : ovh;
                    *(f162*)(dst + o) = __float22half2_rn(
                        make_float2(v0 * s, v1 * s));
                } else if (EPI == EPI_BIAS_RESID) {
                    size_t o = (size_t)m * N + col;
                    float2 r2 = *(const float2*)(resid + o);
                    float2 w2;
                    w2.x = v0 + bias[col]     + r2.x;
                    w2.y = v1 + bias[col + 1] + r2.y;
                    *(float2*)(Cf + o) = w2;
                } else { // EPI_RELU
                    size_t o = (size_t)m * N + col;
                    float u0 = fmaxf(v0 + bias[col],     0.f);
                    float u1 = fmaxf(v1 + bias[col + 1], 0.f);
                    *(f162*)(Of + o) = __float22half2_rn(make_float2(u0, u1));
                }
            }
        }
    }
}

// =============== HMMA flash attention: fp16, log2-domain softmax ===========
// grid (bh=64, qbRev=16): heavy q-blocks launch FIRST (LPT scheduling).
// 2 CTAs/SM (regs capped at 128, smem 48K x2 fits).
// smem: Q 16K | stage0 (K 8K, V 8K) | stage1
#define FL_SMEM (16384 + 2*16384)   // 49152

__global__ void __launch_bounds__(256, 2) flash_hmma(
    const f16* __restrict__ qh, const f16* __restrict__ kh,
    const f16* __restrict__ vh, f16* __restrict__ att)
{
    extern __shared__ char smraw[];
    uint32_t sbase = smem_to_u32(smraw);

    int tid  = threadIdx.x;
    int w    = tid >> 5, lane = tid & 31;
    int g    = lane >> 3, lr = lane & 7;
    int qb   = (int)gridDim.y - 1 - (int)blockIdx.y;   // 15..0: heavy first
    int bh   = blockIdx.x;          // b*16+h
    int b    = bh >> 4, h = bh & 15;

    const f16* qp = qh + ((size_t)bh * TT + qb*128) * DH;
    const f16* kp = kh + (size_t)bh * TT * DH;
    const f16* vp = vh + (size_t)bh * TT * DH;

    const int ntile = 2*qb + 2;

    // ---- initial copies: Q + stage 0 (one group) ----
    {
        #pragma unroll
        for (int it = 0; it < 4; it++) {
            int u = tid + it * 256;
            int r = u >> 3, cc = u & 7;
            uint32_t so = SWZ128((uint32_t)(r*128 + cc*16));
            CP16(sbase + so, qp + (size_t)r * DH + cc*8);
        }
        #pragma unroll
        for (int it = 0; it < 2; it++) {
            int u = tid + it * 256;     // 512 units: 64 rows x 8
            int r = u >> 3, cc = u & 7;
            uint32_t so = SWZ128((uint32_t)(r*128 + cc*16));
            uint32_t st = sbase + 16384;
            CP16(st + so,        kp + (size_t)r * DH + cc*8);
            CP16(st + 8192 + so, vp + (size_t)r * DH + cc*8);
        }
    }
    CP_COMMIT();

    float O[8][4];
    #pragma unroll
    for (int j = 0; j < 8; j++)
        #pragma unroll
        for (int q = 0; q < 4; q++) O[j][q] = 0.f;
    float m0 = -FLT_MAX, m1 = -FLT_MAX, l0 = 0.f, l1 = 0.f;

    int trow0 = qb*128 + w*16 + (lane >> 2);   // token row of c0/c1
    int trow1 = trow0 + 8;                     // token row of c2/c3
    int rowmaxw = qb*128 + w*16 + 15;

    uint32_t qf[4][4];

    for (int kt = 0; kt < ntile; kt++) {
        CP_WAIT(0);                // tile kt (and Q on kt==0) resident
        __syncthreads();           // all warps done with tile kt-1 + visibility
        if (kt + 1 < ntile) {      // slot (kt+1)&1 == slot of kt-1: safe now
            uint32_t st = sbase + 16384 + (uint32_t)((kt+1) & 1) * 16384;
            const f16* kq = kp + (size_t)(kt+1)*64*DH;
            const f16* vq = vp + (size_t)(kt+1)*64*DH;
            #pragma unroll
            for (int it = 0; it < 2; it++) {
                int u = tid + it * 256;
                int r = u >> 3, cc = u & 7;
                uint32_t so = SWZ128((uint32_t)(r*128 + cc*16));
                CP16(st + so,        kq + (size_t)r * DH + cc*8);
                CP16(st + 8192 + so, vq + (size_t)r * DH + cc*8);
            }
            CP_COMMIT();
        }

        if (kt == 0) {
            #pragma unroll
            for (int c = 0; c < 4; c++) {
                uint32_t off = SWZ128((uint32_t)(
                    (w*16 + (g & 1)*8 + lr) * 128 + c*32 + (g >> 1)*16));
                ldsm_x4(sbase + off, qf[c][0], qf[c][1], qf[c][2], qf[c][3]);
            }
        }

        bool active = (kt*64 <= rowmaxw);
        if (active) {
            uint32_t st = sbase + 16384 + (uint32_t)(kt & 1) * 16384;
            uint32_t kB = st, vB = st + 8192;

            // ---- S = Q*K^T  (log2 domain: q pre-scaled by E^-0.5*log2e) ----
            float S[8][4];
            #pragma unroll
            for (int j = 0; j < 8; j++)
                #pragma unroll
                for (int q = 0; q < 4; q++) S[j][q] = 0.f;
            #pragma unroll
            for (int c = 0; c < 4; c++) {
                #pragma unroll
                for (int p = 0; p < 4; p++) {
                    uint32_t off = SWZ128((uint32_t)(
                        (p*16 + (g >> 1)*8 + lr) * 128 + c*32 + (g & 1)*16));
                    uint32_t r0, r1, r2, r3;
                    ldsm_x4(kB + off, r0, r1, r2, r3);
                    uint32_t b0[2] = {r0, r1}, b1[2] = {r2, r3};
                    mma_f16(S[p*2],   qf[c], b0);
                    mma_f16(S[p*2+1], qf[c], b1);
                }
            }

            // ---- causal mask ----
            if (kt*64 + 63 > trow0) {
                #pragma unroll
                for (int j = 0; j < 8; j++) {
                    int c0 = kt*64 + j*8 + (lane & 3)*2;
                    if (c0     > trow0) S[j][0] = -FLT_MAX;
                    if (c0 + 1 > trow0) S[j][1] = -FLT_MAX;
                    if (c0     > trow1) S[j][2] = -FLT_MAX;
                    if (c0 + 1 > trow1) S[j][3] = -FLT_MAX;
                }
            }

            // ---- online softmax (base-2) ----
            float mx0 = -FLT_MAX, mx1 = -FLT_MAX;
            #pragma unroll
            for (int j = 0; j < 8; j++) {
                mx0 = fmaxf(mx0, fmaxf(S[j][0], S[j][1]));
                mx1 = fmaxf(mx1, fmaxf(S[j][2], S[j][3]));
            }
            mx0 = fmaxf(mx0, __shfl_xor_sync(0xffffffffu, mx0, 1));
            mx0 = fmaxf(mx0, __shfl_xor_sync(0xffffffffu, mx0, 2));
            mx1 = fmaxf(mx1, __shfl_xor_sync(0xffffffffu, mx1, 1));
            mx1 = fmaxf(mx1, __shfl_xor_sync(0xffffffffu, mx1, 2));
            float mn0 = fmaxf(m0, mx0), mn1 = fmaxf(m1, mx1);
            float al0 = ex2f(m0 - mn0), al1 = ex2f(m1 - mn1);
            float rs0 = 0.f, rs1 = 0.f;
            #pragma unroll
            for (int j = 0; j < 8; j++) {
                S[j][0] = ex2f(S[j][0] - mn0);
                S[j][1] = ex2f(S[j][1] - mn0);
                S[j][2] = ex2f(S[j][2] - mn1);
                S[j][3] = ex2f(S[j][3] - mn1);
                rs0 += S[j][0] + S[j][1];
                rs1 += S[j][2] + S[j][3];
            }
            rs0 += __shfl_xor_sync(0xffffffffu, rs0, 1);
            rs0 += __shfl_xor_sync(0xffffffffu, rs0, 2);
            rs1 += __shfl_xor_sync(0xffffffffu, rs1, 1);
            rs1 += __shfl_xor_sync(0xffffffffu, rs1, 2);
            l0 = l0 * al0 + rs0;  m0 = mn0;
            l1 = l1 * al1 + rs1;  m1 = mn1;
            #pragma unroll
            for (int j = 0; j < 8; j++) {
                O[j][0] *= al0; O[j][1] *= al0;
                O[j][2] *= al1; O[j][3] *= al1;
            }

            // ---- O += P*V  (V row-major via ldmatrix.trans) ----
            #pragma unroll
            for (int c = 0; c < 4; c++) {
                uint32_t ph[4];
                f162 t0 = __float22half2_rn(make_float2(S[2*c][0],   S[2*c][1]));
                f162 t1 = __float22half2_rn(make_float2(S[2*c][2],   S[2*c][3]));
                f162 t2 = __float22half2_rn(make_float2(S[2*c+1][0], S[2*c+1][1]));
                f162 t3 = __float22half2_rn(make_float2(S[2*c+1][2], S[2*c+1][3]));
                ph[0] = *reinterpret_cast<uint32_t*>(&t0);
                ph[1] = *reinterpret_cast<uint32_t*>(&t1);
                ph[2] = *reinterpret_cast<uint32_t*>(&t2);
                ph[3] = *reinterpret_cast<uint32_t*>(&t3);
                #pragma unroll
                for (int p = 0; p < 4; p++) {
                    uint32_t off = SWZ128((uint32_t)(
                        (c*16 + (g & 1)*8 + lr) * 128 + p*32 + (g >> 1)*16));
                    uint32_t r0, r1, r2, r3;
                    ldsm_x4_trans(vB + off, r0, r1, r2, r3);
                    uint32_t b0[2] = {r0, r1}, b1[2] = {r2, r3};
                    mma_f16(O[p*2],   ph, b0);
                    mma_f16(O[p*2+1], ph, b1);
                }
            }
        }
    }

    // ---- normalize + store att fp16 [B,T,E] ----
    float il0 = 1.0f / l0, il1 = 1.0f / l1;
    #pragma unroll
    for (int j = 0; j < 8; j++) {
        int col = h*64 + j*8 + (lane & 3)*2;
        size_t o_0 = ((size_t)b*TT + trow0) * EE + col;
        size_t o_1 = ((size_t)b*TT + trow1) * EE + col;
        *(f162*)(att + o_0) = __float22half2_rn(
            make_float2(O[j][0]*il0, O[j][1]*il0));
        *(f162*)(att + o_1) = __float22half2_rn(
            make_float2(O[j][2]*il1, O[j][3]*il1));
    }
}

// ============================== launch =====================================
extern "C" void kernel_launch(void* const* d_in, const int* in_sizes, int n_in,
                              void* d_out, int out_size)
{
    const float* x     = (const float*)d_in[0];
    const float* ln1_g = (const float*)d_in[1];
    const float* ln1_b = (const float*)d_in[2];
    const float* Wq    = (const float*)d_in[3];
    const float* Wk    = (const float*)d_in[4];
    const float* Wv    = (const float*)d_in[5];
    const float* Wp    = (const float*)d_in[6];
    const float* bp    = (const float*)d_in[7];
    const float* ln2_g = (const float*)d_in[8];
    const float* ln2_b = (const float*)d_in[9];
    const float* W1    = (const float*)d_in[10];
    const float* b1    = (const float*)d_in[11];
    const float* W2    = (const float*)d_in[12];
    const float* b2    = (const float*)d_in[13];
    float* out = (float*)d_out;

    float *x1;
    f16 *qh_, *kh_, *vh_, *h_, *att_, *ff_;
    f16 *wqT, *WpT, *W1T, *W2T;
    cudaGetSymbolAddress((void**)&x1,  g_x1);
    cudaGetSymbolAddress((void**)&qh_, g_qh);
    cudaGetSymbolAddress((void**)&kh_, g_kh);
    cudaGetSymbolAddress((void**)&vh_, g_vh);
    cudaGetSymbolAddress((void**)&h_,  g_h);
    cudaGetSymbolAddress((void**)&att_, g_att);
    cudaGetSymbolAddress((void**)&ff_, g_ff);
    cudaGetSymbolAddress((void**)&wqT, g_wqkvT);
    cudaGetSymbolAddress((void**)&WpT, g_WpT);
    cudaGetSymbolAddress((void**)&W1T, g_W1T);
    cudaGetSymbolAddress((void**)&W2T, g_W2T);

    cudaFuncSetAttribute(flash_hmma, cudaFuncAttributeMaxDynamicSharedMemorySize, FL_SMEM);
    cudaFuncSetAttribute(gemm_tc<EPI_QKV>,        cudaFuncAttributeMaxDynamicSharedMemorySize, SMEM_GEMM);
    cudaFuncSetAttribute(gemm_tc<EPI_BIAS_RESID>, cudaFuncAttributeMaxDynamicSharedMemorySize, SMEM_GEMM);
    cudaFuncSetAttribute(gemm_tc<EPI_RELU>,       cudaFuncAttributeMaxDynamicSharedMemorySize, SMEM_GEMM);

    // 0. fused prep: LN1 + all weight transposes/converts (one launch)
    prep_kernel<<<PREP_BLOCKS, 256>>>(
        x, ln1_g, ln1_b, h_,
        Wq, Wk, Wv, wqT, Wp, WpT, W1, W1T, W2, W2T);
    // 1. QKV projection -> q (scaled by E^-0.5*log2e) / k / v fp16
    gemm_tc<EPI_QKV><<<dim3(3072/128, MROWS/128), 256, SMEM_GEMM>>>(
        h_, wqT, 1024, 3072, nullptr, nullptr,
        nullptr, nullptr, qh_, kh_, vh_);
    // 2. flash attention -> att fp16 (LPT: heavy q-blocks first)
    flash_hmma<<<dim3(BB*HH, TT/128), 256, FL_SMEM>>>(qh_, kh_, vh_, att_);
    // 3. out-proj + bias + residual -> x1 fp32
    gemm_tc<EPI_BIAS_RESID><<<dim3(1024/128, MROWS/128), 256, SMEM_GEMM>>>(
        att_, WpT, 1024, 1024, bp, x,
        x1, nullptr, nullptr, nullptr, nullptr);
    // 4. LN2 -> fp16
    ln_kernel<<<MROWS, 256>>>(x1, ln2_g, ln2_b, h_);
    // 5. FFN up + relu -> ff fp16
    gemm_tc<EPI_RELU><<<dim3(4096/128, MROWS/128), 256, SMEM_GEMM>>>(
        h_, W1T, 1024, 4096, b1, nullptr,
        nullptr, ff_, nullptr, nullptr, nullptr);
    // 6. FFN down + bias + residual -> out fp32
    gemm_tc<EPI_BIAS_RESID><<<dim3(1024/128, MROWS/128), 256, SMEM_GEMM>>>(
        ff_, W2T, 4096, 1024, b2, x1,
        out, nullptr, nullptr, nullptr, nullptr);
}

// round 15
// speedup vs baseline: 1.2894x; 1.2894x over previous
#include <cuda_runtime.h>
#include <cuda_fp16.h>
#include <cfloat>
#include <cstdint>
#include <math.h>

#define BB 4
#define TT 2048
#define EE 1024
#define HH 16
#define DH 64
#define MROWS (BB*TT)        // 8192

typedef __half  f16;
typedef __half2 f162;

// ============================ scratch =====================================
__device__ float g_x1 [(size_t)MROWS*EE];
__device__ f16  g_qh  [(size_t)BB*HH*TT*DH];
__device__ f16  g_kh  [(size_t)BB*HH*TT*DH];
__device__ f16  g_vh  [(size_t)BB*HH*TT*DH];
__device__ f16  g_h   [(size_t)MROWS*EE];
__device__ f16  g_att [(size_t)MROWS*EE];
__device__ f16  g_ff  [(size_t)MROWS*4096];
__device__ f16  g_wqkvT[(size_t)3072*EE];
__device__ f16  g_WpT[(size_t)EE*EE];
__device__ f16  g_W1T[(size_t)4096*EE];
__device__ f16  g_W2T[(size_t)EE*4096];

// ============================ helpers =====================================
__device__ __forceinline__ uint32_t smem_to_u32(const void* p) {
    uint32_t a;
    asm("{ .reg .u64 t; cvta.to.shared.u64 t, %1; cvt.u32.u64 %0, t; }"
        : "=r"(a) : "l"(p));
    return a;
}

#define SWZ128(o) ((o) ^ (((o) >> 3) & 0x70))

#define CP16(dst, src) \
    asm volatile("cp.async.cg.shared.global [%0], [%1], 16;" \
        :: "r"(dst), "l"(src) : "memory")
#define CP_COMMIT() asm volatile("cp.async.commit_group;" ::: "memory")
#define CP_WAIT(N)  asm volatile("cp.async.wait_group %0;" :: "n"(N) : "memory")

__device__ __forceinline__ void ldsm_x4(uint32_t addr,
    uint32_t& r0, uint32_t& r1, uint32_t& r2, uint32_t& r3) {
    asm volatile("ldmatrix.sync.aligned.m8n8.x4.shared.b16 {%0,%1,%2,%3}, [%4];"
        : "=r"(r0), "=r"(r1), "=r"(r2), "=r"(r3) : "r"(addr));
}
__device__ __forceinline__ void ldsm_x4_trans(uint32_t addr,
    uint32_t& r0, uint32_t& r1, uint32_t& r2, uint32_t& r3) {
    asm volatile("ldmatrix.sync.aligned.m8n8.x4.trans.shared.b16 {%0,%1,%2,%3}, [%4];"
        : "=r"(r0), "=r"(r1), "=r"(r2), "=r"(r3) : "r"(addr));
}

__device__ __forceinline__ void mma_f16(float* c, const uint32_t* a, const uint32_t* b) {
    asm volatile(
        "mma.sync.aligned.m16n8k16.row.col.f32.f16.f16.f32 "
        "{%0,%1,%2,%3}, {%4,%5,%6,%7}, {%8,%9}, {%0,%1,%2,%3};"
        : "+f"(c[0]), "+f"(c[1]), "+f"(c[2]), "+f"(c[3])
        : "r"(a[0]), "r"(a[1]), "r"(a[2]), "r"(a[3]), "r"(b[0]), "r"(b[1]));
}

__device__ __forceinline__ float ex2f(float x) {
    float y;
    asm("ex2.approx.ftz.f32 %0, %1;" : "=f"(y) : "f"(x));
    return y;
}

// ============================ LayerNorm body ================================
__device__ __forceinline__ void ln_body(
    const float* __restrict__ x, const float* __restrict__ g,
    const float* __restrict__ b, f16* __restrict__ oh,
    int row, float* sred)
{
    int tid = threadIdx.x;
    float4 xv = ((const float4*)(x + (size_t)row * EE))[tid];
    float s  = xv.x + xv.y + xv.z + xv.w;
    float s2 = xv.x*xv.x + xv.y*xv.y + xv.z*xv.z + xv.w*xv.w;
    #pragma unroll
    for (int o = 16; o > 0; o >>= 1) {
        s  += __shfl_xor_sync(0xffffffffu, s,  o);
        s2 += __shfl_xor_sync(0xffffffffu, s2, o);
    }
    float* rs = sred;
    float* rs2 = sred + 8;
    int w = tid >> 5;
    if ((tid & 31) == 0) { rs[w] = s; rs2[w] = s2; }
    __syncthreads();
    s = 0.f; s2 = 0.f;
    #pragma unroll
    for (int i = 0; i < 8; i++) { s += rs[i]; s2 += rs2[i]; }
    float mean = s * (1.0f/1024.0f);
    float var  = s2 * (1.0f/1024.0f) - mean*mean;
    float inv  = rsqrtf(var + 1e-5f);
    float4 gv = ((const float4*)g)[tid];
    float4 bv = ((const float4*)b)[tid];
    float o0 = (xv.x - mean)*inv*gv.x + bv.x;
    float o1 = (xv.y - mean)*inv*gv.y + bv.y;
    float o2 = (xv.z - mean)*inv*gv.z + bv.z;
    float o3 = (xv.w - mean)*inv*gv.w + bv.w;
    size_t base = (size_t)row * EE + tid*4;
    *(f162*)(oh+base)   = __float22half2_rn(make_float2(o0,o1));
    *(f162*)(oh+base+2) = __float22half2_rn(make_float2(o2,o3));
}

// ============== transpose+convert body: fp32 [K,N] -> fp16 [N,K] ===========
__device__ __forceinline__ void convt_body(
    const float* __restrict__ src, f16* __restrict__ dh, int K, int N,
    int bx, int by, float* tbuf)
{
    float (*t)[33] = (float (*)[33]) tbuf;
    int x = threadIdx.x & 31, y = threadIdx.x >> 5;
    int n0 = bx * 32, k0 = by * 32;
    #pragma unroll
    for (int i = 0; i < 32; i += 8)
        t[y+i][x] = src[(size_t)(k0 + y + i) * N + n0 + x];
    __syncthreads();
    #pragma unroll
    for (int i = 0; i < 32; i += 8) {
        float vv = t[x][y+i];
        dh[(size_t)(n0 + y + i) * K + k0 + x] = __float2half_rn(vv);
    }
}

// ==== fused prep: LN1 + qkv-weight pack/transpose + 3 weight converts ======
#define PREP_BLOCKS (8192 + 3072 + 1024 + 4096 + 4096)

__global__ void __launch_bounds__(256) prep_kernel(
    const float* __restrict__ x, const float* __restrict__ ln1_g,
    const float* __restrict__ ln1_b, f16* __restrict__ h_,
    const float* __restrict__ Wq, const float* __restrict__ Wk,
    const float* __restrict__ Wv, f16* __restrict__ wqT,
    const float* __restrict__ Wp, f16* __restrict__ WpT,
    const float* __restrict__ W1, f16* __restrict__ W1T,
    const float* __restrict__ W2, f16* __restrict__ W2T)
{
    __shared__ float sbuf[32*33];
    int bid = blockIdx.x;
    if (bid < 8192) {
        ln_body(x, ln1_g, ln1_b, h_, bid, sbuf);
        return;
    }
    bid -= 8192;
    if (bid < 3072) {
        float (*t)[33] = (float (*)[33]) sbuf;
        int xx = threadIdx.x & 31, yy = threadIdx.x >> 5;
        int bx = bid & 31;
        int byz = bid >> 5;
        int by = byz & 1;
        int z  = byz >> 1;
        int tq = z >> 4, hh2 = z & 15;
        const float* W = (tq == 0) ? Wq : (tq == 1) ? Wk : Wv;
        int e0 = bx * 32, d0 = by * 32;
        #pragma unroll
        for (int i = 0; i < 32; i += 8)
            t[yy+i][xx] = W[(size_t)hh2 * EE * DH + (size_t)(e0 + yy + i) * DH + d0 + xx];
        __syncthreads();
        #pragma unroll
        for (int i = 0; i < 32; i += 8) {
            int rown = tq*1024 + hh2*64 + d0 + yy + i;
            wqT[(size_t)rown * EE + e0 + xx] = __float2half_rn(t[xx][yy+i]);
        }
        return;
    }
    bid -= 3072;
    if (bid < 1024) { convt_body(Wp, WpT, 1024, 1024, bid & 31, bid >> 5, sbuf); return; }
    bid -= 1024;
    if (bid < 4096) { convt_body(W1, W1T, 1024, 4096, bid & 127, bid >> 7, sbuf); return; }
    bid -= 4096;
    convt_body(W2, W2T, 4096, 1024, bid & 31, bid >> 5, sbuf);
}

// ==================== standalone LN (for LN2) ==============================
__global__ void __launch_bounds__(256) ln_kernel(
    const float* __restrict__ x, const float* __restrict__ g,
    const float* __restrict__ b, f16* __restrict__ oh)
{
    __shared__ float sred[16];
    ln_body(x, g, b, oh, blockIdx.x, sred);
}

// ===== HMMA GEMM: C[M,N] = A[M,K] * B[N,K]^T, fp16, 128x128 tile, 3-stage ==
// 256 threads / 8 warps, warp tile 32x64 (acc 64 regs). 2 CTAs per SM.
// (R13 configuration — best verified GEMM on the legacy mma.sync path.)
enum { EPI_QKV = 0, EPI_BIAS_RESID = 1, EPI_RELU = 2 };

#define KCHUNK 64
#define A_TILE_BYTES 16384                // 128 rows x 64 fp16
#define B_TILE_BYTES 16384                // 128 rows x 64 fp16
#define STAGE_BYTES (A_TILE_BYTES + B_TILE_BYTES)   // 32768
#define NSTAGE 3
#define SMEM_GEMM (NSTAGE*STAGE_BYTES + 1024)       // 99328

template<int EPI>
__global__ void __launch_bounds__(256, 2) gemm_tc(
    const f16* __restrict__ A, const f16* __restrict__ B,
    int K, int N,
    const float* __restrict__ bias, const float* __restrict__ resid,
    float* __restrict__ Cf, f16* __restrict__ Of,
    f16* __restrict__ oqh, f16* __restrict__ okh, f16* __restrict__ ovh)
{
    extern __shared__ char smraw[];
    uint32_t raw = smem_to_u32(smraw);
    uint32_t sbase = (raw + 1023u) & ~1023u;

    int tid  = threadIdx.x;
    int wid  = tid >> 5, lane = tid & 31;
    int m0 = blockIdx.y * 128;
    int n0 = blockIdx.x * 128;
    int mw = (wid & 3) * 32;       // warp row offset (4 warps in M)
    int nw = (wid >> 2) * 64;      // warp col offset (2 warps in N)

    const f16* Ap = A + (size_t)m0 * K;
    const f16* Bp = B + (size_t)n0 * K;

    const int nk = K / KCHUNK;

    auto prefetch = [&](int c) {
        uint32_t st = sbase + (uint32_t)(c % NSTAGE) * STAGE_BYTES;
        int kc = c * KCHUNK;
        #pragma unroll
        for (int it = 0; it < 4; it++) {          // A: 1024 16B units
            int u = tid + it * 256;
            int r = u >> 3, cc = u & 7;
            uint32_t so = st + SWZ128((uint32_t)(r * 128 + cc * 16));
            CP16(so, Ap + (size_t)r * K + kc + cc * 8);
        }
        #pragma unroll
        for (int it = 0; it < 4; it++) {          // B: 1024 16B units
            int u = tid + it * 256;
            int r = u >> 3, cc = u & 7;
            uint32_t so = st + A_TILE_BYTES + SWZ128((uint32_t)(r * 128 + cc * 16));
            CP16(so, Bp + (size_t)r * K + kc + cc * 8);
        }
    };

    float acc[2][8][4];
    #pragma unroll
    for (int mt = 0; mt < 2; mt++)
        #pragma unroll
        for (int nt = 0; nt < 8; nt++)
            #pragma unroll
            for (int q = 0; q < 4; q++) acc[mt][nt][q] = 0.f;

    prefetch(0); CP_COMMIT();
    prefetch(1); CP_COMMIT();

    int g  = lane >> 3;   // ldmatrix lane group
    int lr = lane & 7;

    for (int c = 0; c < nk; c++) {
        CP_WAIT(1);                 // chunk c resident (c+1 may fly)
        __syncthreads();            // all warps past chunk c-1 reads + visibility
        if (c + 2 < nk) { prefetch(c + 2); CP_COMMIT(); }   // slot (c-1)%3: safe

        uint32_t st = sbase + (uint32_t)(c % NSTAGE) * STAGE_BYTES;
        uint32_t aB = st, bB = st + A_TILE_BYTES;

        #pragma unroll
        for (int ks = 0; ks < 4; ks++) {
            uint32_t ah[2][4], bh[8][2];
            #pragma unroll
            for (int mt = 0; mt < 2; mt++) {
                uint32_t off = SWZ128((uint32_t)(
                    (mw + mt*16 + (g & 1)*8 + lr) * 128 + ks*32 + (g >> 1)*16));
                ldsm_x4(aB + off, ah[mt][0], ah[mt][1], ah[mt][2], ah[mt][3]);
            }
            #pragma unroll
            for (int p = 0; p < 4; p++) {
                uint32_t off = SWZ128((uint32_t)(
                    (nw + p*16 + (g >> 1)*8 + lr) * 128 + ks*32 + (g & 1)*16));
                uint32_t r0, r1, r2, r3;
                ldsm_x4(bB + off, r0, r1, r2, r3);
                bh[p*2][0] = r0; bh[p*2][1] = r1;
                bh[p*2+1][0] = r2; bh[p*2+1][1] = r3;
            }
            #pragma unroll
            for (int mt = 0; mt < 2; mt++)
                #pragma unroll
                for (int nt = 0; nt < 8; nt++)
                    mma_f16(acc[mt][nt], ah[mt], bh[nt]);
        }
    }

    // ------------------------------ epilogue -------------------------------
    int qr = lane >> 2;        // 0..7
    int qc = (lane & 3) * 2;   // 0,2,4,6
    #pragma unroll
    for (int mt = 0; mt < 2; mt++) {
        #pragma unroll
        for (int nt = 0; nt < 8; nt++) {
            int col = n0 + nw + nt*8 + qc;
            #pragma unroll
            for (int half = 0; half < 2; half++) {
                int m = m0 + mw + mt*16 + qr + half*8;
                float v0 = acc[mt][nt][half*2 + 0];
                float v1 = acc[mt][nt][half*2 + 1];
                if (EPI == EPI_QKV) {
                    int bb = m >> 11, tt = m & 2047;
                    int t = col >> 10, nn = col & 1023, h = nn >> 6, d0 = nn & 63;
                    size_t o = (((size_t)(bb*HH + h)) * TT + tt) * DH + d0;
                    // q pre-scaled by E^-0.5 * log2(e) for ex2-softmax
                    float s = (t == 0) ? 0.045084439f : 1.0f;
                    f16* dst = (t == 0) ? oqh : (t == 1) ? okh : ovh;
                    *(f162*)(dst + o) = __float22half2_rn(
                        make_float2(v0 * s, v1 * s));
                } else if (EPI == EPI_BIAS_RESID) {
                    size_t o = (size_t)m * N + col;
                    float2 r2 = *(const float2*)(resid + o);
                    float2 w2;
                    w2.x = v0 + bias[col]     + r2.x;
                    w2.y = v1 + bias[col + 1] + r2.y;
                    *(float2*)(Cf + o) = w2;
                } else { // EPI_RELU
                    size_t o = (size_t)m * N + col;
                    float u0 = fmaxf(v0 + bias[col],     0.f);
                    float u1 = fmaxf(v1 + bias[col + 1], 0.f);
                    *(f162*)(Of + o) = __float22half2_rn(make_float2(u0, u1));
                }
            }
        }
    }
}

// =============== HMMA flash attention: fp16, log2-domain softmax ===========
// grid (bh=64, qbRev=16): heavy q-blocks launch FIRST (LPT scheduling).
// 2 CTAs/SM. 3-stage K/V ring: two tiles in flight while computing a third.
// smem: Q 16K | ring slot0 (K 8K, V 8K) | slot1 | slot2 = 64K
#define FL_SMEM (16384 + 3*16384)   // 65536

__global__ void __launch_bounds__(256, 2) flash_hmma(
    const f16* __restrict__ qh, const f16* __restrict__ kh,
    const f16* __restrict__ vh, f16* __restrict__ att)
{
    extern __shared__ char smraw[];
    uint32_t sbase = smem_to_u32(smraw);

    int tid  = threadIdx.x;
    int w    = tid >> 5, lane = tid & 31;
    int g    = lane >> 3, lr = lane & 7;
    int qb   = (int)gridDim.y - 1 - (int)blockIdx.y;   // 15..0: heavy first
    int bh   = blockIdx.x;          // b*16+h
    int b    = bh >> 4, h = bh & 15;

    const f16* qp = qh + ((size_t)bh * TT + qb*128) * DH;
    const f16* kp = kh + (size_t)bh * TT * DH;
    const f16* vp = vh + (size_t)bh * TT * DH;

    const int ntile = 2*qb + 2;

    auto load_tile = [&](int kt) {                     // into ring slot kt%3
        uint32_t st = sbase + 16384 + (uint32_t)(kt % 3) * 16384;
        const f16* kq = kp + (size_t)kt*64*DH;
        const f16* vq = vp + (size_t)kt*64*DH;
        #pragma unroll
        for (int it = 0; it < 2; it++) {
            int u = tid + it * 256;
            int r = u >> 3, cc = u & 7;
            uint32_t so = SWZ128((uint32_t)(r*128 + cc*16));
            CP16(st + so,        kq + (size_t)r * DH + cc*8);
            CP16(st + 8192 + so, vq + (size_t)r * DH + cc*8);
        }
    };

    // ---- initial copies: group0 = Q + tile0; group1 = tile1 ----
    {
        #pragma unroll
        for (int it = 0; it < 4; it++) {
            int u = tid + it * 256;
            int r = u >> 3, cc = u & 7;
            uint32_t so = SWZ128((uint32_t)(r*128 + cc*16));
            CP16(sbase + so, qp + (size_t)r * DH + cc*8);
        }
        load_tile(0);
    }
    CP_COMMIT();
    load_tile(1);            // ntile >= 2 always
    CP_COMMIT();

    float O[8][4];
    #pragma unroll
    for (int j = 0; j < 8; j++)
        #pragma unroll
        for (int q = 0; q < 4; q++) O[j][q] = 0.f;
    float m0 = -FLT_MAX, m1 = -FLT_MAX, l0 = 0.f, l1 = 0.f;

    int trow0 = qb*128 + w*16 + (lane >> 2);   // token row of c0/c1
    int trow1 = trow0 + 8;                     // token row of c2/c3
    int rowmaxw = qb*128 + w*16 + 15;

    uint32_t qf[4][4];

    for (int kt = 0; kt < ntile; kt++) {
        CP_WAIT(1);                // tile kt (and Q on kt==0) resident; kt+1 may fly
        __syncthreads();           // all warps done reading tile kt-1 + visibility
        if (kt + 2 < ntile) {      // ring slot (kt+2)%3 == slot (kt-1)%3: safe now
            load_tile(kt + 2);
            CP_COMMIT();
        }

        if (kt == 0) {
            #pragma unroll
            for (int c = 0; c < 4; c++) {
                uint32_t off = SWZ128((uint32_t)(
                    (w*16 + (g & 1)*8 + lr) * 128 + c*32 + (g >> 1)*16));
                ldsm_x4(sbase + off, qf[c][0], qf[c][1], qf[c][2], qf[c][3]);
            }
        }

        bool active = (kt*64 <= rowmaxw);
        if (active) {
            uint32_t st = sbase + 16384 + (uint32_t)(kt % 3) * 16384;
            uint32_t kB = st, vB = st + 8192;

            // ---- S = Q*K^T  (log2 domain: q pre-scaled by E^-0.5*log2e) ----
            float S[8][4];
            #pragma unroll
            for (int j = 0; j < 8; j++)
                #pragma unroll
                for (int q = 0; q < 4; q++) S[j][q] = 0.f;
            #pragma unroll
            for (int c = 0; c < 4; c++) {
                #pragma unroll
                for (int p = 0; p < 4; p++) {
                    uint32_t off = SWZ128((uint32_t)(
                        (p*16 + (g >> 1)*8 + lr) * 128 + c*32 + (g & 1)*16));
                    uint32_t r0, r1, r2, r3;
                    ldsm_x4(kB + off, r0, r1, r2, r3);
                    uint32_t b0[2] = {r0, r1}, b1[2] = {r2, r3};
                    mma_f16(S[p*2],   qf[c], b0);
                    mma_f16(S[p*2+1], qf[c], b1);
                }
            }

            // ---- causal mask ----
            if (kt*64 + 63 > trow0) {
                #pragma unroll
                for (int j = 0; j < 8; j++) {
                    int c0 = kt*64 + j*8 + (lane & 3)*2;
                    if (c0     > trow0) S[j][0] = -FLT_MAX;
                    if (c0 + 1 > trow0) S[j][1] = -FLT_MAX;
                    if (c0     > trow1) S[j][2] = -FLT_MAX;
                    if (c0 + 1 > trow1) S[j][3] = -FLT_MAX;
                }
            }

            // ---- online softmax (base-2) ----
            float mx0 = -FLT_MAX, mx1 = -FLT_MAX;
            #pragma unroll
            for (int j = 0; j < 8; j++) {
                mx0 = fmaxf(mx0, fmaxf(S[j][0], S[j][1]));
                mx1 = fmaxf(mx1, fmaxf(S[j][2], S[j][3]));
            }
            mx0 = fmaxf(mx0, __shfl_xor_sync(0xffffffffu, mx0, 1));
            mx0 = fmaxf(mx0, __shfl_xor_sync(0xffffffffu, mx0, 2));
            mx1 = fmaxf(mx1, __shfl_xor_sync(0xffffffffu, mx1, 1));
            mx1 = fmaxf(mx1, __shfl_xor_sync(0xffffffffu, mx1, 2));
            float mn0 = fmaxf(m0, mx0), mn1 = fmaxf(m1, mx1);
            float al0 = ex2f(m0 - mn0), al1 = ex2f(m1 - mn1);
            float rs0 = 0.f, rs1 = 0.f;
            #pragma unroll
            for (int j = 0; j < 8; j++) {
                S[j][0] = ex2f(S[j][0] - mn0);
                S[j][1] = ex2f(S[j][1] - mn0);
                S[j][2] = ex2f(S[j][2] - mn1);
                S[j][3] = ex2f(S[j][3] - mn1);
                rs0 += S[j][0] + S[j][1];
                rs1 += S[j][2] + S[j][3];
            }
            rs0 += __shfl_xor_sync(0xffffffffu, rs0, 1);
            rs0 += __shfl_xor_sync(0xffffffffu, rs0, 2);
            rs1 += __shfl_xor_sync(0xffffffffu, rs1, 1);
            rs1 += __shfl_xor_sync(0xffffffffu, rs1, 2);
            l0 = l0 * al0 + rs0;  m0 = mn0;
            l1 = l1 * al1 + rs1;  m1 = mn1;
            #pragma unroll
            for (int j = 0; j < 8; j++) {
                O[j][0] *= al0; O[j][1] *= al0;
                O[j][2] *= al1; O[j][3] *= al1;
            }

            // ---- O += P*V  (V row-major via ldmatrix.trans) ----
            #pragma unroll
            for (int c = 0; c < 4; c++) {
                uint32_t ph[4];
                f162 t0 = __float22half2_rn(make_float2(S[2*c][0],   S[2*c][1]));
                f162 t1 = __float22half2_rn(make_float2(S[2*c][2],   S[2*c][3]));
                f162 t2 = __float22half2_rn(make_float2(S[2*c+1][0], S[2*c+1][1]));
                f162 t3 = __float22half2_rn(make_float2(S[2*c+1][2], S[2*c+1][3]));
                ph[0] = *reinterpret_cast<uint32_t*>(&t0);
                ph[1] = *reinterpret_cast<uint32_t*>(&t1);
                ph[2] = *reinterpret_cast<uint32_t*>(&t2);
                ph[3] = *reinterpret_cast<uint32_t*>(&t3);
                #pragma unroll
                for (int p = 0; p < 4; p++) {
                    uint32_t off = SWZ128((uint32_t)(
                        (c*16 + (g & 1)*8 + lr) * 128 + p*32 + (g >> 1)*16));
                    uint32_t r0, r1, r2, r3;
                    ldsm_x4_trans(vB + off, r0, r1, r2, r3);
                    uint32_t b0[2] = {r0, r1}, b1[2] = {r2, r3};
                    mma_f16(O[p*2],   ph, b0);
                    mma_f16(O[p*2+1], ph, b1);
                }
            }
        }
    }

    // ---- normalize + store att fp16 [B,T,E] ----
    float il0 = 1.0f / l0, il1 = 1.0f / l1;
    #pragma unroll
    for (int j = 0; j < 8; j++) {
        int col = h*64 + j*8 + (lane & 3)*2;
        size_t o_0 = ((size_t)b*TT + trow0) * EE + col;
        size_t o_1 = ((size_t)b*TT + trow1) * EE + col;
        *(f162*)(att + o_0) = __float22half2_rn(
            make_float2(O[j][0]*il0, O[j][1]*il0));
        *(f162*)(att + o_1) = __float22half2_rn(
            make_float2(O[j][2]*il1, O[j][3]*il1));
    }
}

// ============================== launch =====================================
extern "C" void kernel_launch(void* const* d_in, const int* in_sizes, int n_in,
                              void* d_out, int out_size)
{
    const float* x     = (const float*)d_in[0];
    const float* ln1_g = (const float*)d_in[1];
    const float* ln1_b = (const float*)d_in[2];
    const float* Wq    = (const float*)d_in[3];
    const float* Wk    = (const float*)d_in[4];
    const float* Wv    = (const float*)d_in[5];
    const float* Wp    = (const float*)d_in[6];
    const float* bp    = (const float*)d_in[7];
    const float* ln2_g = (const float*)d_in[8];
    const float* ln2_b = (const float*)d_in[9];
    const float* W1    = (const float*)d_in[10];
    const float* b1    = (const float*)d_in[11];
    const float* W2    = (const float*)d_in[12];
    const float* b2    = (const float*)d_in[13];
    float* out = (float*)d_out;

    float *x1;
    f16 *qh_, *kh_, *vh_, *h_, *att_, *ff_;
    f16 *wqT, *WpT, *W1T, *W2T;
    cudaGetSymbolAddress((void**)&x1,  g_x1);
    cudaGetSymbolAddress((void**)&qh_, g_qh);
    cudaGetSymbolAddress((void**)&kh_, g_kh);
    cudaGetSymbolAddress((void**)&vh_, g_vh);
    cudaGetSymbolAddress((void**)&h_,  g_h);
    cudaGetSymbolAddress((void**)&att_, g_att);
    cudaGetSymbolAddress((void**)&ff_, g_ff);
    cudaGetSymbolAddress((void**)&wqT, g_wqkvT);
    cudaGetSymbolAddress((void**)&WpT, g_WpT);
    cudaGetSymbolAddress((void**)&W1T, g_W1T);
    cudaGetSymbolAddress((void**)&W2T, g_W2T);

    cudaFuncSetAttribute(flash_hmma, cudaFuncAttributeMaxDynamicSharedMemorySize, FL_SMEM);
    cudaFuncSetAttribute(gemm_tc<EPI_QKV>,        cudaFuncAttributeMaxDynamicSharedMemorySize, SMEM_GEMM);
    cudaFuncSetAttribute(gemm_tc<EPI_BIAS_RESID>, cudaFuncAttributeMaxDynamicSharedMemorySize, SMEM_GEMM);
    cudaFuncSetAttribute(gemm_tc<EPI_RELU>,       cudaFuncAttributeMaxDynamicSharedMemorySize, SMEM_GEMM);

    // 0. fused prep: LN1 + all weight transposes/converts (one launch)
    prep_kernel<<<PREP_BLOCKS, 256>>>(
        x, ln1_g, ln1_b, h_,
        Wq, Wk, Wv, wqT, Wp, WpT, W1, W1T, W2, W2T);
    // 1. QKV projection -> q (scaled by E^-0.5*log2e) / k / v fp16
    gemm_tc<EPI_QKV><<<dim3(3072/128, MROWS/128), 256, SMEM_GEMM>>>(
        h_, wqT, 1024, 3072, nullptr, nullptr,
        nullptr, nullptr, qh_, kh_, vh_);
    // 2. flash attention -> att fp16 (LPT: heavy q-blocks first)
    flash_hmma<<<dim3(BB*HH, TT/128), 256, FL_SMEM>>>(qh_, kh_, vh_, att_);
    // 3. out-proj + bias + residual -> x1 fp32
    gemm_tc<EPI_BIAS_RESID><<<dim3(1024/128, MROWS/128), 256, SMEM_GEMM>>>(
        att_, WpT, 1024, 1024, bp, x,
        x1, nullptr, nullptr, nullptr, nullptr);
    // 4. LN2 -> fp16
    ln_kernel<<<MROWS, 256>>>(x1, ln2_g, ln2_b, h_);
    // 5. FFN up + relu -> ff fp16
    gemm_tc<EPI_RELU><<<dim3(4096/128, MROWS/128), 256, SMEM_GEMM>>>(
        h_, W1T, 1024, 4096, b1, nullptr,
        nullptr, ff_, nullptr, nullptr, nullptr);
    // 6. FFN down + bias + residual -> out fp32
    gemm_tc<EPI_BIAS_RESID><<<dim3(1024/128, MROWS/128), 256, SMEM_GEMM>>>(
        ff_, W2T, 4096, 1024, b2, x1,
        out, nullptr, nullptr, nullptr, nullptr);
}

// round 16
// speedup vs baseline: 1.2930x; 1.0028x over previous
#include <cuda_runtime.h>
#include <cuda_fp16.h>
#include <cfloat>
#include <cstdint>
#include <math.h>

#define BB 4
#define TT 2048
#define EE 1024
#define HH 16
#define DH 64
#define MROWS (BB*TT)        // 8192

typedef __half  f16;
typedef __half2 f162;

// ============================ scratch =====================================
__device__ float g_x1 [(size_t)MROWS*EE];
__device__ f16  g_qh  [(size_t)BB*HH*TT*DH];
__device__ f16  g_kh  [(size_t)BB*HH*TT*DH];
__device__ f16  g_vh  [(size_t)BB*HH*TT*DH];
__device__ f16  g_h   [(size_t)MROWS*EE];
__device__ f16  g_att [(size_t)MROWS*EE];
__device__ f16  g_ff  [(size_t)MROWS*4096];
__device__ f16  g_wqkvT[(size_t)3072*EE];
__device__ f16  g_WpT[(size_t)EE*EE];
__device__ f16  g_W1T[(size_t)4096*EE];
__device__ f16  g_W2T[(size_t)EE*4096];

// ============================ helpers =====================================
__device__ __forceinline__ uint32_t smem_to_u32(const void* p) {
    uint32_t a;
    asm("{ .reg .u64 t; cvta.to.shared.u64 t, %1; cvt.u32.u64 %0, t; }"
        : "=r"(a) : "l"(p));
    return a;
}

#define SWZ128(o) ((o) ^ (((o) >> 3) & 0x70))

#define CP16(dst, src) \
    asm volatile("cp.async.cg.shared.global [%0], [%1], 16;" \
        :: "r"(dst), "l"(src) : "memory")
#define CP_COMMIT() asm volatile("cp.async.commit_group;" ::: "memory")
#define CP_WAIT(N)  asm volatile("cp.async.wait_group %0;" :: "n"(N) : "memory")

__device__ __forceinline__ void ldsm_x4(uint32_t addr,
    uint32_t& r0, uint32_t& r1, uint32_t& r2, uint32_t& r3) {
    asm volatile("ldmatrix.sync.aligned.m8n8.x4.shared.b16 {%0,%1,%2,%3}, [%4];"
        : "=r"(r0), "=r"(r1), "=r"(r2), "=r"(r3) : "r"(addr));
}
__device__ __forceinline__ void ldsm_x4_trans(uint32_t addr,
    uint32_t& r0, uint32_t& r1, uint32_t& r2, uint32_t& r3) {
    asm volatile("ldmatrix.sync.aligned.m8n8.x4.trans.shared.b16 {%0,%1,%2,%3}, [%4];"
        : "=r"(r0), "=r"(r1), "=r"(r2), "=r"(r3) : "r"(addr));
}

__device__ __forceinline__ void mma_f16(float* c, const uint32_t* a, const uint32_t* b) {
    asm volatile(
        "mma.sync.aligned.m16n8k16.row.col.f32.f16.f16.f32 "
        "{%0,%1,%2,%3}, {%4,%5,%6,%7}, {%8,%9}, {%0,%1,%2,%3};"
        : "+f"(c[0]), "+f"(c[1]), "+f"(c[2]), "+f"(c[3])
        : "r"(a[0]), "r"(a[1]), "r"(a[2]), "r"(a[3]), "r"(b[0]), "r"(b[1]));
}

__device__ __forceinline__ float ex2f(float x) {
    float y;
    asm("ex2.approx.ftz.f32 %0, %1;" : "=f"(y) : "f"(x));
    return y;
}

// ============================ LayerNorm body ================================
__device__ __forceinline__ void ln_body(
    const float* __restrict__ x, const float* __restrict__ g,
    const float* __restrict__ b, f16* __restrict__ oh,
    int row, float* sred)
{
    int tid = threadIdx.x;
    float4 xv = ((const float4*)(x + (size_t)row * EE))[tid];
    float s  = xv.x + xv.y + xv.z + xv.w;
    float s2 = xv.x*xv.x + xv.y*xv.y + xv.z*xv.z + xv.w*xv.w;
    #pragma unroll
    for (int o = 16; o > 0; o >>= 1) {
        s  += __shfl_xor_sync(0xffffffffu, s,  o);
        s2 += __shfl_xor_sync(0xffffffffu, s2, o);
    }
    float* rs = sred;
    float* rs2 = sred + 8;
    int w = tid >> 5;
    if ((tid & 31) == 0) { rs[w] = s; rs2[w] = s2; }
    __syncthreads();
    s = 0.f; s2 = 0.f;
    #pragma unroll
    for (int i = 0; i < 8; i++) { s += rs[i]; s2 += rs2[i]; }
    float mean = s * (1.0f/1024.0f);
    float var  = s2 * (1.0f/1024.0f) - mean*mean;
    float inv  = rsqrtf(var + 1e-5f);
    float4 gv = ((const float4*)g)[tid];
    float4 bv = ((const float4*)b)[tid];
    float o0 = (xv.x - mean)*inv*gv.x + bv.x;
    float o1 = (xv.y - mean)*inv*gv.y + bv.y;
    float o2 = (xv.z - mean)*inv*gv.z + bv.z;
    float o3 = (xv.w - mean)*inv*gv.w + bv.w;
    size_t base = (size_t)row * EE + tid*4;
    *(f162*)(oh+base)   = __float22half2_rn(make_float2(o0,o1));
    *(f162*)(oh+base+2) = __float22half2_rn(make_float2(o2,o3));
}

// ============== transpose+convert body: fp32 [K,N] -> fp16 [N,K] ===========
__device__ __forceinline__ void convt_body(
    const float* __restrict__ src, f16* __restrict__ dh, int K, int N,
    int bx, int by, float* tbuf)
{
    float (*t)[33] = (float (*)[33]) tbuf;
    int x = threadIdx.x & 31, y = threadIdx.x >> 5;
    int n0 = bx * 32, k0 = by * 32;
    #pragma unroll
    for (int i = 0; i < 32; i += 8)
        t[y+i][x] = src[(size_t)(k0 + y + i) * N + n0 + x];
    __syncthreads();
    #pragma unroll
    for (int i = 0; i < 32; i += 8) {
        float vv = t[x][y+i];
        dh[(size_t)(n0 + y + i) * K + k0 + x] = __float2half_rn(vv);
    }
}

// ==== fused prep: LN1 + qkv-weight pack/transpose + 3 weight converts ======
#define PREP_BLOCKS (8192 + 3072 + 1024 + 4096 + 4096)

__global__ void __launch_bounds__(256) prep_kernel(
    const float* __restrict__ x, const float* __restrict__ ln1_g,
    const float* __restrict__ ln1_b, f16* __restrict__ h_,
    const float* __restrict__ Wq, const float* __restrict__ Wk,
    const float* __restrict__ Wv, f16* __restrict__ wqT,
    const float* __restrict__ Wp, f16* __restrict__ WpT,
    const float* __restrict__ W1, f16* __restrict__ W1T,
    const float* __restrict__ W2, f16* __restrict__ W2T)
{
    __shared__ float sbuf[32*33];
    int bid = blockIdx.x;
    if (bid < 8192) {
        ln_body(x, ln1_g, ln1_b, h_, bid, sbuf);
        return;
    }
    bid -= 8192;
    if (bid < 3072) {
        float (*t)[33] = (float (*)[33]) sbuf;
        int xx = threadIdx.x & 31, yy = threadIdx.x >> 5;
        int bx = bid & 31;
        int byz = bid >> 5;
        int by = byz & 1;
        int z  = byz >> 1;
        int tq = z >> 4, hh2 = z & 15;
        const float* W = (tq == 0) ? Wq : (tq == 1) ? Wk : Wv;
        int e0 = bx * 32, d0 = by * 32;
        #pragma unroll
        for (int i = 0; i < 32; i += 8)
            t[yy+i][xx] = W[(size_t)hh2 * EE * DH + (size_t)(e0 + yy + i) * DH + d0 + xx];
        __syncthreads();
        #pragma unroll
        for (int i = 0; i < 32; i += 8) {
            int rown = tq*1024 + hh2*64 + d0 + yy + i;
            wqT[(size_t)rown * EE + e0 + xx] = __float2half_rn(t[xx][yy+i]);
        }
        return;
    }
    bid -= 3072;
    if (bid < 1024) { convt_body(Wp, WpT, 1024, 1024, bid & 31, bid >> 5, sbuf); return; }
    bid -= 1024;
    if (bid < 4096) { convt_body(W1, W1T, 1024, 4096, bid & 127, bid >> 7, sbuf); return; }
    bid -= 4096;
    convt_body(W2, W2T, 4096, 1024, bid & 31, bid >> 5, sbuf);
}

// ==================== standalone LN (for LN2) ==============================
__global__ void __launch_bounds__(256) ln_kernel(
    const float* __restrict__ x, const float* __restrict__ g,
    const float* __restrict__ b, f16* __restrict__ oh)
{
    __shared__ float sred[16];
    ln_body(x, g, b, oh, blockIdx.x, sred);
}

// ===== HMMA GEMM: C[M,N] = A[M,K] * B[N,K]^T, fp16, 128x128 tile, 3-stage ==
// 256 threads / 8 warps, warp tile 32x64 (acc 64 regs). 2 CTAs per SM with
// independent barrier domains (best verified config, R13).
enum { EPI_QKV = 0, EPI_BIAS_RESID = 1, EPI_RELU = 2 };

#define KCHUNK 64
#define A_TILE_BYTES 16384                // 128 rows x 64 fp16
#define B_TILE_BYTES 16384                // 128 rows x 64 fp16
#define STAGE_BYTES (A_TILE_BYTES + B_TILE_BYTES)   // 32768
#define NSTAGE 3
#define SMEM_GEMM (NSTAGE*STAGE_BYTES + 1024)       // 99328

template<int EPI>
__global__ void __launch_bounds__(256, 2) gemm_tc(
    const f16* __restrict__ A, const f16* __restrict__ B,
    int K, int N,
    const float* __restrict__ bias, const float* __restrict__ resid,
    float* __restrict__ Cf, f16* __restrict__ Of,
    f16* __restrict__ oqh, f16* __restrict__ okh, f16* __restrict__ ovh)
{
    extern __shared__ char smraw[];
    uint32_t raw = smem_to_u32(smraw);
    uint32_t sbase = (raw + 1023u) & ~1023u;

    int tid  = threadIdx.x;
    int wid  = tid >> 5, lane = tid & 31;
    int m0 = blockIdx.y * 128;
    int n0 = blockIdx.x * 128;
    int mw = (wid & 3) * 32;       // warp row offset (4 warps in M)
    int nw = (wid >> 2) * 64;      // warp col offset (2 warps in N)

    const f16* Ap = A + (size_t)m0 * K;
    const f16* Bp = B + (size_t)n0 * K;

    const int nk = K / KCHUNK;

    auto prefetch = [&](int c) {
        uint32_t st = sbase + (uint32_t)(c % NSTAGE) * STAGE_BYTES;
        int kc = c * KCHUNK;
        #pragma unroll
        for (int it = 0; it < 4; it++) {          // A: 1024 16B units
            int u = tid + it * 256;
            int r = u >> 3, cc = u & 7;
            uint32_t so = st + SWZ128((uint32_t)(r * 128 + cc * 16));
            CP16(so, Ap + (size_t)r * K + kc + cc * 8);
        }
        #pragma unroll
        for (int it = 0; it < 4; it++) {          // B: 1024 16B units
            int u = tid + it * 256;
            int r = u >> 3, cc = u & 7;
            uint32_t so = st + A_TILE_BYTES + SWZ128((uint32_t)(r * 128 + cc * 16));
            CP16(so, Bp + (size_t)r * K + kc + cc * 8);
        }
    };

    float acc[2][8][4];
    #pragma unroll
    for (int mt = 0; mt < 2; mt++)
        #pragma unroll
        for (int nt = 0; nt < 8; nt++)
            #pragma unroll
            for (int q = 0; q < 4; q++) acc[mt][nt][q] = 0.f;

    prefetch(0); CP_COMMIT();
    prefetch(1); CP_COMMIT();

    int g  = lane >> 3;   // ldmatrix lane group
    int lr = lane & 7;

    for (int c = 0; c < nk; c++) {
        CP_WAIT(1);                 // chunk c resident (c+1 may fly)
        __syncthreads();            // all warps past chunk c-1 reads + visibility
        if (c + 2 < nk) { prefetch(c + 2); CP_COMMIT(); }   // slot (c-1)%3: safe

        uint32_t st = sbase + (uint32_t)(c % NSTAGE) * STAGE_BYTES;
        uint32_t aB = st, bB = st + A_TILE_BYTES;

        #pragma unroll
        for (int ks = 0; ks < 4; ks++) {
            uint32_t ah[2][4], bh[8][2];
            #pragma unroll
            for (int mt = 0; mt < 2; mt++) {
                uint32_t off = SWZ128((uint32_t)(
                    (mw + mt*16 + (g & 1)*8 + lr) * 128 + ks*32 + (g >> 1)*16));
                ldsm_x4(aB + off, ah[mt][0], ah[mt][1], ah[mt][2], ah[mt][3]);
            }
            #pragma unroll
            for (int p = 0; p < 4; p++) {
                uint32_t off = SWZ128((uint32_t)(
                    (nw + p*16 + (g >> 1)*8 + lr) * 128 + ks*32 + (g & 1)*16));
                uint32_t r0, r1, r2, r3;
                ldsm_x4(bB + off, r0, r1, r2, r3);
                bh[p*2][0] = r0; bh[p*2][1] = r1;
                bh[p*2+1][0] = r2; bh[p*2+1][1] = r3;
            }
            #pragma unroll
            for (int mt = 0; mt < 2; mt++)
                #pragma unroll
                for (int nt = 0; nt < 8; nt++)
                    mma_f16(acc[mt][nt], ah[mt], bh[nt]);
        }
    }

    // ------------------------------ epilogue -------------------------------
    int qr = lane >> 2;        // 0..7
    int qc = (lane & 3) * 2;   // 0,2,4,6
    #pragma unroll
    for (int mt = 0; mt < 2; mt++) {
        #pragma unroll
        for (int nt = 0; nt < 8; nt++) {
            int col = n0 + nw + nt*8 + qc;
            #pragma unroll
            for (int half = 0; half < 2; half++) {
                int m = m0 + mw + mt*16 + qr + half*8;
                float v0 = acc[mt][nt][half*2 + 0];
                float v1 = acc[mt][nt][half*2 + 1];
                if (EPI == EPI_QKV) {
                    int bb = m >> 11, tt = m & 2047;
                    int t = col >> 10, nn = col & 1023, h = nn >> 6, d0 = nn & 63;
                    size_t o = (((size_t)(bb*HH + h)) * TT + tt) * DH + d0;
                    // q pre-scaled by E^-0.5 * log2(e) for ex2-softmax
                    float s = (t == 0) ? 0.045084439f : 1.0f;
                    f16* dst = (t == 0) ? oqh : (t == 1) ? okh : ovh;
                    *(f162*)(dst + o) = __float22half2_rn(
                        make_float2(v0 * s, v1 * s));
                } else if (EPI == EPI_BIAS_RESID) {
                    size_t o = (size_t)m * N + col;
                    float2 r2 = *(const float2*)(resid + o);
                    float2 w2;
                    w2.x = v0 + bias[col]     + r2.x;
                    w2.y = v1 + bias[col + 1] + r2.y;
                    *(float2*)(Cf + o) = w2;
                } else { // EPI_RELU
                    size_t o = (size_t)m * N + col;
                    float u0 = fmaxf(v0 + bias[col],     0.f);
                    float u1 = fmaxf(v1 + bias[col + 1], 0.f);
                    *(f162*)(Of + o) = __float22half2_rn(make_float2(u0, u1));
                }
            }
        }
    }
}

// =============== HMMA flash attention: fp16, log2-domain softmax ===========
// grid (bh=64, qbRev=16): heavy q-blocks launch FIRST (LPT scheduling).
// 2 CTAs/SM. smem: Q 16K | stage0 (K 8K, V 8K) | stage1
#define FL_SMEM (16384 + 2*16384)   // 49152

__global__ void __launch_bounds__(256, 2) flash_hmma(
    const f16* __restrict__ qh, const f16* __restrict__ kh,
    const f16* __restrict__ vh, f16* __restrict__ att)
{
    extern __shared__ char smraw[];
    uint32_t sbase = smem_to_u32(smraw);

    int tid  = threadIdx.x;
    int w    = tid >> 5, lane = tid & 31;
    int g    = lane >> 3, lr = lane & 7;
    int qb   = (int)gridDim.y - 1 - (int)blockIdx.y;   // 15..0: heavy first
    int bh   = blockIdx.x;          // b*16+h
    int b    = bh >> 4, h = bh & 15;

    const f16* qp = qh + ((size_t)bh * TT + qb*128) * DH;
    const f16* kp = kh + (size_t)bh * TT * DH;
    const f16* vp = vh + (size_t)bh * TT * DH;

    const int ntile = 2*qb + 2;

    // ---- initial copies: Q + stage 0 (one group) ----
    {
        #pragma unroll
        for (int it = 0; it < 4; it++) {
            int u = tid + it * 256;
            int r = u >> 3, cc = u & 7;
            uint32_t so = SWZ128((uint32_t)(r*128 + cc*16));
            CP16(sbase + so, qp + (size_t)r * DH + cc*8);
        }
        #pragma unroll
        for (int it = 0; it < 2; it++) {
            int u = tid + it * 256;     // 512 units: 64 rows x 8
            int r = u >> 3, cc = u & 7;
            uint32_t so = SWZ128((uint32_t)(r*128 + cc*16));
            uint32_t st = sbase + 16384;
            CP16(st + so,        kp + (size_t)r * DH + cc*8);
            CP16(st + 8192 + so, vp + (size_t)r * DH + cc*8);
        }
    }
    CP_COMMIT();

    float O[8][4];
    #pragma unroll
    for (int j = 0; j < 8; j++)
        #pragma unroll
        for (int q = 0; q < 4; q++) O[j][q] = 0.f;
    float m0 = -FLT_MAX, m1 = -FLT_MAX, l0 = 0.f, l1 = 0.f;

    int trow0 = qb*128 + w*16 + (lane >> 2);   // token row of c0/c1
    int trow1 = trow0 + 8;                     // token row of c2/c3
    int rowmaxw = qb*128 + w*16 + 15;

    uint32_t qf[4][4];

    for (int kt = 0; kt < ntile; kt++) {
        CP_WAIT(0);                // tile kt (and Q on kt==0) resident
        __syncthreads();           // all warps done with tile kt-1 + visibility
        if (kt + 1 < ntile) {      // slot (kt+1)&1 == slot of kt-1: safe now
            uint32_t st = sbase + 16384 + (uint32_t)((kt+1) & 1) * 16384;
            const f16* kq = kp + (size_t)(kt+1)*64*DH;
            const f16* vq = vp + (size_t)(kt+1)*64*DH;
            #pragma unroll
            for (int it = 0; it < 2; it++) {
                int u = tid + it * 256;
                int r = u >> 3, cc = u & 7;
                uint32_t so = SWZ128((uint32_t)(r*128 + cc*16));
                CP16(st + so,        kq + (size_t)r * DH + cc*8);
                CP16(st + 8192 + so, vq + (size_t)r * DH + cc*8);
            }
            CP_COMMIT();
        }

        if (kt == 0) {
            #pragma unroll
            for (int c = 0; c < 4; c++) {
                uint32_t off = SWZ128((uint32_t)(
                    (w*16 + (g & 1)*8 + lr) * 128 + c*32 + (g >> 1)*16));
                ldsm_x4(sbase + off, qf[c][0], qf[c][1], qf[c][2], qf[c][3]);
            }
        }

        bool active = (kt*64 <= rowmaxw);
        if (active) {
            uint32_t st = sbase + 16384 + (uint32_t)(kt & 1) * 16384;
            uint32_t kB = st, vB = st + 8192;

            // ---- S = Q*K^T  (log2 domain: q pre-scaled by E^-0.5*log2e) ----
            float S[8][4];
            #pragma unroll
            for (int j = 0; j < 8; j++)
                #pragma unroll
                for (int q = 0; q < 4; q++) S[j][q] = 0.f;
            #pragma unroll
            for (int c = 0; c < 4; c++) {
                #pragma unroll
                for (int p = 0; p < 4; p++) {
                    uint32_t off = SWZ128((uint32_t)(
                        (p*16 + (g >> 1)*8 + lr) * 128 + c*32 + (g & 1)*16));
                    uint32_t r0, r1, r2, r3;
                    ldsm_x4(kB + off, r0, r1, r2, r3);
                    uint32_t b0[2] = {r0, r1}, b1[2] = {r2, r3};
                    mma_f16(S[p*2],   qf[c], b0);
                    mma_f16(S[p*2+1], qf[c], b1);
                }
            }

            // ---- causal mask ----
            if (kt*64 + 63 > trow0) {
                #pragma unroll
                for (int j = 0; j < 8; j++) {
                    int c0 = kt*64 + j*8 + (lane & 3)*2;
                    if (c0     > trow0) S[j][0] = -FLT_MAX;
                    if (c0 + 1 > trow0) S[j][1] = -FLT_MAX;
                    if (c0     > trow1) S[j][2] = -FLT_MAX;
                    if (c0 + 1 > trow1) S[j][3] = -FLT_MAX;
                }
            }

            // ---- online softmax (base-2) ----
            float mx0 = -FLT_MAX, mx1 = -FLT_MAX;
            #pragma unroll
            for (int j = 0; j < 8; j++) {
                mx0 = fmaxf(mx0, fmaxf(S[j][0], S[j][1]));
                mx1 = fmaxf(mx1, fmaxf(S[j][2], S[j][3]));
            }
            mx0 = fmaxf(mx0, __shfl_xor_sync(0xffffffffu, mx0, 1));
            mx0 = fmaxf(mx0, __shfl_xor_sync(0xffffffffu, mx0, 2));
            mx1 = fmaxf(mx1, __shfl_xor_sync(0xffffffffu, mx1, 1));
            mx1 = fmaxf(mx1, __shfl_xor_sync(0xffffffffu, mx1, 2));
            float mn0 = fmaxf(m0, mx0), mn1 = fmaxf(m1, mx1);
            float al0 = ex2f(m0 - mn0), al1 = ex2f(m1 - mn1);
            float rs0 = 0.f, rs1 = 0.f;
            #pragma unroll
            for (int j = 0; j < 8; j++) {
                S[j][0] = ex2f(S[j][0] - mn0);
                S[j][1] = ex2f(S[j][1] - mn0);
                S[j][2] = ex2f(S[j][2] - mn1);
                S[j][3] = ex2f(S[j][3] - mn1);
                rs0 += S[j][0] + S[j][1];
                rs1 += S[j][2] + S[j][3];
            }
            rs0 += __shfl_xor_sync(0xffffffffu, rs0, 1);
            rs0 += __shfl_xor_sync(0xffffffffu, rs0, 2);
            rs1 += __shfl_xor_sync(0xffffffffu, rs1, 1);
            rs1 += __shfl_xor_sync(0xffffffffu, rs1, 2);
            l0 = l0 * al0 + rs0;  m0 = mn0;
            l1 = l1 * al1 + rs1;  m1 = mn1;
            #pragma unroll
            for (int j = 0; j < 8; j++) {
                O[j][0] *= al0; O[j][1] *= al0;
                O[j][2] *= al1; O[j][3] *= al1;
            }

            // ---- O += P*V  (V row-major via ldmatrix.trans) ----
            #pragma unroll
            for (int c = 0; c < 4; c++) {
                uint32_t ph[4];
                f162 t0 = __float22half2_rn(make_float2(S[2*c][0],   S[2*c][1]));
                f162 t1 = __float22half2_rn(make_float2(S[2*c][2],   S[2*c][3]));
                f162 t2 = __float22half2_rn(make_float2(S[2*c+1][0], S[2*c+1][1]));
                f162 t3 = __float22half2_rn(make_float2(S[2*c+1][2], S[2*c+1][3]));
                ph[0] = *reinterpret_cast<uint32_t*>(&t0);
                ph[1] = *reinterpret_cast<uint32_t*>(&t1);
                ph[2] = *reinterpret_cast<uint32_t*>(&t2);
                ph[3] = *reinterpret_cast<uint32_t*>(&t3);
                #pragma unroll
                for (int p = 0; p < 4; p++) {
                    uint32_t off = SWZ128((uint32_t)(
                        (c*16 + (g & 1)*8 + lr) * 128 + p*32 + (g >> 1)*16));
                    uint32_t r0, r1, r2, r3;
                    ldsm_x4_trans(vB + off, r0, r1, r2, r3);
                    uint32_t b0[2] = {r0, r1}, b1[2] = {r2, r3};
                    mma_f16(O[p*2],   ph, b0);
                    mma_f16(O[p*2+1], ph, b1);
                }
            }
        }
    }

    // ---- normalize + store att fp16 [B,T,E] ----
    float il0 = 1.0f / l0, il1 = 1.0f / l1;
    #pragma unroll
    for (int j = 0; j < 8; j++) {
        int col = h*64 + j*8 + (lane & 3)*2;
        size_t o_0 = ((size_t)b*TT + trow0) * EE + col;
        size_t o_1 = ((size_t)b*TT + trow1) * EE + col;
        *(f162*)(att + o_0) = __float22half2_rn(
            make_float2(O[j][0]*il0, O[j][1]*il0));
        *(f162*)(att + o_1) = __float22half2_rn(
            make_float2(O[j][2]*il1, O[j][3]*il1));
    }
}

// ============================== launch =====================================
extern "C" void kernel_launch(void* const* d_in, const int* in_sizes, int n_in,
                              void* d_out, int out_size)
{
    const float* x     = (const float*)d_in[0];
    const float* ln1_g = (const float*)d_in[1];
    const float* ln1_b = (const float*)d_in[2];
    const float* Wq    = (const float*)d_in[3];
    const float* Wk    = (const float*)d_in[4];
    const float* Wv    = (const float*)d_in[5];
    const float* Wp    = (const float*)d_in[6];
    const float* bp    = (const float*)d_in[7];
    const float* ln2_g = (const float*)d_in[8];
    const float* ln2_b = (const float*)d_in[9];
    const float* W1    = (const float*)d_in[10];
    const float* b1    = (const float*)d_in[11];
    const float* W2    = (const float*)d_in[12];
    const float* b2    = (const float*)d_in[13];
    float* out = (float*)d_out;

    float *x1;
    f16 *qh_, *kh_, *vh_, *h_, *att_, *ff_;
    f16 *wqT, *WpT, *W1T, *W2T;
    cudaGetSymbolAddress((void**)&x1,  g_x1);
    cudaGetSymbolAddress((void**)&qh_, g_qh);
    cudaGetSymbolAddress((void**)&kh_, g_kh);
    cudaGetSymbolAddress((void**)&vh_, g_vh);
    cudaGetSymbolAddress((void**)&h_,  g_h);
    cudaGetSymbolAddress((void**)&att_, g_att);
    cudaGetSymbolAddress((void**)&ff_, g_ff);
    cudaGetSymbolAddress((void**)&wqT, g_wqkvT);
    cudaGetSymbolAddress((void**)&WpT, g_WpT);
    cudaGetSymbolAddress((void**)&W1T, g_W1T);
    cudaGetSymbolAddress((void**)&W2T, g_W2T);

    cudaFuncSetAttribute(flash_hmma, cudaFuncAttributeMaxDynamicSharedMemorySize, FL_SMEM);
    cudaFuncSetAttribute(gemm_tc<EPI_QKV>,        cudaFuncAttributeMaxDynamicSharedMemorySize, SMEM_GEMM);
    cudaFuncSetAttribute(gemm_tc<EPI_BIAS_RESID>, cudaFuncAttributeMaxDynamicSharedMemorySize, SMEM_GEMM);
    cudaFuncSetAttribute(gemm_tc<EPI_RELU>,       cudaFuncAttributeMaxDynamicSharedMemorySize, SMEM_GEMM);

    // 0. fused prep: LN1 + all weight transposes/converts (one launch)
    prep_kernel<<<PREP_BLOCKS, 256>>>(
        x, ln1_g, ln1_b, h_,
        Wq, Wk, Wv, wqT, Wp, WpT, W1, W1T, W2, W2T);
    // 1. QKV projection -> q (scaled by E^-0.5*log2e) / k / v fp16
    gemm_tc<EPI_QKV><<<dim3(3072/128, MROWS/128), 256, SMEM_GEMM>>>(
        h_, wqT, 1024, 3072, nullptr, nullptr,
        nullptr, nullptr, qh_, kh_, vh_);
    // 2. flash attention -> att fp16 (LPT: heavy q-blocks first)
    flash_hmma<<<dim3(BB*HH, TT/128), 256, FL_SMEM>>>(qh_, kh_, vh_, att_);
    // 3. out-proj + bias + residual -> x1 fp32
    gemm_tc<EPI_BIAS_RESID><<<dim3(1024/128, MROWS/128), 256, SMEM_GEMM>>>(
        att_, WpT, 1024, 1024, bp, x,
        x1, nullptr, nullptr, nullptr, nullptr);
    // 4. LN2 -> fp16
    ln_kernel<<<MROWS, 256>>>(x1, ln2_g, ln2_b, h_);
    // 5. FFN up + relu -> ff fp16
    gemm_tc<EPI_RELU><<<dim3(4096/128, MROWS/128), 256, SMEM_GEMM>>>(
        h_, W1T, 1024, 4096, b1, nullptr,
        nullptr, ff_, nullptr, nullptr, nullptr);
    // 6. FFN down + bias + residual -> out fp32
    gemm_tc<EPI_BIAS_RESID><<<dim3(1024/128, MROWS/128), 256, SMEM_GEMM>>>(
        ff_, W2T, 4096, 1024, b2, x1,
        out, nullptr, nullptr, nullptr, nullptr);
}